// round 2
// baseline (speedup 1.0000x reference)
#include <cuda_runtime.h>
#include <stdint.h>

// BurgerDissipativeLossOperator
// inputs (metadata order):
//   d_in[0] x_t        float32 (N_NODES, 2)   -> 8,000,000 elems
//   d_in[1] x_t1       float32 (N_NODES, 2)
//   d_in[2] edge_index int32   (2, N_EDGES)   -> 16,000,000 elems (JAX x64 off)
//   d_in[3] edge_attr  float32 (N_EDGES, 1)
//   d_in[4] mask       float32 (N_NODES, 1)
// output: loss float32 (N_NODES,)

#define N_NODES 4000000
#define N_EDGES 8000000
#define INV_DT  100.0f   // 1/0.01
#define MU      0.01f

// scratch (device globals; no runtime allocation allowed)
__device__ float g_sum[N_NODES];
__device__ float g_cnt[N_NODES];
__device__ float g_du[N_NODES];

// ---------------------------------------------------------------------------
__global__ void k_zero() {
    int i = blockIdx.x * blockDim.x + threadIdx.x;
    if (i < N_NODES) {
        g_sum[i] = 0.0f;
        g_cnt[i] = 0.0f;
    }
}

// pass 1: diff = (u_t1[dst] - u_t1[src]) / len ; segment-sum + counts over dst
__global__ void k_edge1(const int* __restrict__ ei,
                        const float* __restrict__ x_t1,
                        const float* __restrict__ attr) {
    int e = blockIdx.x * blockDim.x + threadIdx.x;
    if (e >= N_EDGES) return;
    int s = ei[e];
    int d = ei[N_EDGES + e];
    float len = attr[e];
    // u_t1 = x_t1[:, 0] -> stride 2
    float diff = (__ldg(&x_t1[2 * d]) - __ldg(&x_t1[2 * s])) / len;
    atomicAdd(&g_sum[d], diff);
    atomicAdd(&g_cnt[d], 1.0f);
}

// du = sum / max(cnt, 1); also re-zero g_sum for the second pass
__global__ void k_du() {
    int i = blockIdx.x * blockDim.x + threadIdx.x;
    if (i < N_NODES) {
        float c = fmaxf(g_cnt[i], 1.0f);
        g_du[i] = g_sum[i] / c;
        g_sum[i] = 0.0f;
    }
}

// pass 2: diff = (du[dst] - du[src]) / len ; segment-sum over dst (cnt reused)
__global__ void k_edge2(const int* __restrict__ ei,
                        const float* __restrict__ attr) {
    int e = blockIdx.x * blockDim.x + threadIdx.x;
    if (e >= N_EDGES) return;
    int s = ei[e];
    int d = ei[N_EDGES + e];
    float len = attr[e];
    float diff = (__ldg(&g_du[d]) - __ldg(&g_du[s])) / len;
    atomicAdd(&g_sum[d], diff);
}

// epilogue: loss = ((u_t - u_t1)/dt + du*u_t1 - MU*d2u) * mask
__global__ void k_final(const float* __restrict__ x_t,
                        const float* __restrict__ x_t1,
                        const float* __restrict__ mask,
                        float* __restrict__ out) {
    int i = blockIdx.x * blockDim.x + threadIdx.x;
    if (i < N_NODES) {
        float ut  = x_t[2 * i];
        float ut1 = x_t1[2 * i];
        float c   = fmaxf(g_cnt[i], 1.0f);
        float d2u = g_sum[i] / c;
        float du  = g_du[i];
        float loss = (ut - ut1) * INV_DT + du * ut1 - MU * d2u;
        out[i] = loss * mask[i];
    }
}

// ---------------------------------------------------------------------------
extern "C" void kernel_launch(void* const* d_in, const int* in_sizes, int n_in,
                              void* d_out, int out_size) {
    const float* x_t  = (const float*)d_in[0];
    const float* x_t1 = (const float*)d_in[1];
    const int*   ei   = (const int*)d_in[2];
    const float* attr = (const float*)d_in[3];
    const float* mask = (const float*)d_in[4];
    float*       out  = (float*)d_out;

    const int TB = 256;
    const int gn = (N_NODES + TB - 1) / TB;
    const int ge = (N_EDGES + TB - 1) / TB;

    k_zero <<<gn, TB>>>();
    k_edge1<<<ge, TB>>>(ei, x_t1, attr);
    k_du   <<<gn, TB>>>();
    k_edge2<<<ge, TB>>>(ei, attr);
    k_final<<<gn, TB>>>(x_t, x_t1, mask, out);
}